// round 16
// baseline (speedup 1.0000x reference)
#include <cuda_runtime.h>
#include <cuda_bf16.h>
#include <math.h>

typedef __nv_bfloat16 bf16;

#define B_    8
#define NQ_   1024
#define DV_   512
#define MROWS (B_ * NQ_)
#define SSTRIDE 40
#define BUFE (128 * SSTRIDE)
#define BUFB (BUFE * 2)
#define SCALE_ 0.04419417382415922f

__device__ bf16  g_Qhi[MROWS * DV_];
__device__ bf16  g_Qlo[MROWS * DV_];
__device__ bf16  g_Khi[MROWS * DV_];
__device__ bf16  g_Wqt_hi[DV_ * DV_];
__device__ bf16  g_Wqt_lo[DV_ * DV_];
__device__ bf16  g_Wkt[DV_ * DV_];
__device__ bf16  g_Wvt[DV_ * DV_];
__device__ bf16  g_Wot_hi[DV_ * DV_];
__device__ bf16  g_Wot_lo[DV_ * DV_];
__device__ float g_Qp [MROWS * DV_];
__device__ bf16  g_Qpb[MROWS * DV_];
__device__ bf16  g_Kpb[MROWS * DV_];
__device__ bf16  g_Vpb[MROWS * DV_];
__device__ float g_Oh [MROWS * DV_];
__device__ float g_X1 [MROWS * DV_];
__device__ bf16  g_X1hi[MROWS * DV_];
__device__ bf16  g_X1lo[MROWS * DV_];
__device__ float g_Y  [MROWS * DV_];

__device__ __forceinline__ unsigned smem_u32(const void* p) {
    unsigned a;
    asm("{ .reg .u64 t; cvta.to.shared.u64 t, %1; cvt.u32.u64 %0, t; }" : "=r"(a) : "l"(p));
    return a;
}
__device__ __forceinline__ unsigned pack2bf(float a, float b) {
    __nv_bfloat162 t = __floats2bfloat162_rn(a, b);
    return *reinterpret_cast<unsigned*>(&t);
}

#define LDSM_X4(R0, R1, R2, R3, ADDR) \
    asm volatile("ldmatrix.sync.aligned.m8n8.x4.shared.b16 {%0,%1,%2,%3}, [%4];" \
                 : "=r"(R0), "=r"(R1), "=r"(R2), "=r"(R3) : "r"(ADDR))

#define LDSM_X4T(R0, R1, R2, R3, ADDR) \
    asm volatile("ldmatrix.sync.aligned.m8n8.x4.trans.shared.b16 {%0,%1,%2,%3}, [%4];" \
                 : "=r"(R0), "=r"(R1), "=r"(R2), "=r"(R3) : "r"(ADDR))

#define MMA16816(D, A, Bb) \
    asm volatile("mma.sync.aligned.m16n8k16.row.col.f32.bf16.bf16.f32 " \
                 "{%0,%1,%2,%3}, {%4,%5,%6,%7}, {%8,%9}, {%0,%1,%2,%3};" \
                 : "+f"((D)[0]), "+f"((D)[1]), "+f"((D)[2]), "+f"((D)[3]) \
                 : "r"((A)[0]), "r"((A)[1]), "r"((A)[2]), "r"((A)[3]), \
                   "r"((Bb)[0]), "r"((Bb)[1]))

#define CPA16(DST, SRC) \
    asm volatile("cp.async.cg.shared.global [%0], [%1], 16;" :: "r"(DST), "l"(SRC))
#define CPA_COMMIT() asm volatile("cp.async.commit_group;")
#define CPA_WAIT1()  asm volatile("cp.async.wait_group 1;")
#define CPA_WAIT0()  asm volatile("cp.async.wait_group 0;")

// Block tile 128x128, 8 warps (4m x 2n), K=512 in chunks of 32.
// cp.async double-buffered: prefetch, commit, WAIT1, sync, compute, sync.
__device__ __forceinline__ void mainloop(
    const bf16* __restrict__ A, const bf16* __restrict__ B,
    bf16* As, bf16* Bs, float (*acc)[4])
{
    const int tid  = threadIdx.x;
    const int l    = tid & 31;
    const int warp = tid >> 5;
    const int wm   = warp & 3, wn = warp >> 2;
    const unsigned sAu = smem_u32(As), sBu = smem_u32(Bs);

    const int ar0 = tid >> 2, ac0 = tid & 3;
    const int ar1 = ar0 + 64;
    const unsigned so0 = (unsigned)((ar0 * SSTRIDE + ac0 * 8) * 2);
    const unsigned so1 = (unsigned)((ar1 * SSTRIDE + ac0 * 8) * 2);

    unsigned aAddr[2];
#pragma unroll
    for (int mt = 0; mt < 2; mt++)
        aAddr[mt] = sAu + (unsigned)(((wm * 32 + mt * 16 + (l & 15)) * SSTRIDE
                                      + (l >> 4) * 8) * 2);
    const int g = l >> 3, l8 = l & 7;
    unsigned bAddr[4];
#pragma unroll
    for (int j = 0; j < 4; j++) {
        int row = wn * 64 + j * 16 + (g >> 1) * 8 + l8;
        bAddr[j] = sBu + (unsigned)((row * SSTRIDE + (g & 1) * 8) * 2);
    }

    CPA16(sAu + so0, A + (size_t)ar0 * 512 + ac0 * 8);
    CPA16(sAu + so1, A + (size_t)ar1 * 512 + ac0 * 8);
    CPA16(sBu + so0, B + (size_t)ar0 * 512 + ac0 * 8);
    CPA16(sBu + so1, B + (size_t)ar1 * 512 + ac0 * 8);
    CPA_COMMIT();

    for (int kc = 0; kc < 16; kc++) {
        if (kc + 1 < 16) {
            const int ko = (kc + 1) * 32;
            const unsigned bo = (unsigned)((kc + 1) & 1) * BUFB;
            CPA16(sAu + bo + so0, A + (size_t)ar0 * 512 + ko + ac0 * 8);
            CPA16(sAu + bo + so1, A + (size_t)ar1 * 512 + ko + ac0 * 8);
            CPA16(sBu + bo + so0, B + (size_t)ar0 * 512 + ko + ac0 * 8);
            CPA16(sBu + bo + so1, B + (size_t)ar1 * 512 + ko + ac0 * 8);
            CPA_COMMIT();
            CPA_WAIT1();
        } else {
            CPA_WAIT0();
        }
        __syncthreads();
        const unsigned bo = (unsigned)(kc & 1) * BUFB;
#pragma unroll
        for (int s = 0; s < 2; s++) {
            unsigned af[2][4];
            LDSM_X4(af[0][0], af[0][1], af[0][2], af[0][3], aAddr[0] + bo + s * 32);
            LDSM_X4(af[1][0], af[1][1], af[1][2], af[1][3], aAddr[1] + bo + s * 32);
            unsigned bfm[8][2];
#pragma unroll
            for (int j = 0; j < 4; j++)
                LDSM_X4(bfm[2 * j][0], bfm[2 * j][1],
                        bfm[2 * j + 1][0], bfm[2 * j + 1][1], bAddr[j] + bo + s * 32);
#pragma unroll
            for (int mt = 0; mt < 2; mt++)
#pragma unroll
                for (int nt = 0; nt < 8; nt++)
                    MMA16816(acc[mt * 8 + nt], af[mt], bfm[nt]);
        }
        __syncthreads();
    }
}

// Merged Q/K/V projections: z=0 -> Qp (3-pass split, f32 + scaled bf16),
// z=1 -> Kp (1-pass, bf16), z=2 -> Vp (1-pass, bf16)
__global__ __launch_bounds__(256, 2) void gemm_qkv(
    const float* __restrict__ bq, const float* __restrict__ bk,
    const float* __restrict__ bv)
{
    __shared__ bf16 As[2 * BUFE], Bs[2 * BUFE];
    float acc[16][4];
#pragma unroll
    for (int i = 0; i < 16; i++)
#pragma unroll
        for (int j = 0; j < 4; j++) acc[i][j] = 0.f;

    const int m0 = blockIdx.y * 128, n0 = blockIdx.x * 128;
    const int z = blockIdx.z;

    if (z == 0) {
        for (int p = 0; p < 3; p++) {
            const bf16* Ag = ((p == 2) ? g_Qlo : g_Qhi) + (size_t)m0 * 512;
            const bf16* Bg = ((p == 1) ? g_Wqt_lo : g_Wqt_hi) + (size_t)n0 * 512;
            mainloop(Ag, Bg, As, Bs, acc);
        }
    } else {
        const bf16* Bw = (z == 1) ? g_Wkt : g_Wvt;
        mainloop(g_Khi + (size_t)m0 * 512, Bw + (size_t)n0 * 512, As, Bs, acc);
    }

    const float* bias = (z == 0) ? bq : (z == 1) ? bk : bv;
    bf16* outB = (z == 0) ? g_Qpb : (z == 1) ? g_Kpb : g_Vpb;

    const int tid = threadIdx.x, l = tid & 31, warp = tid >> 5;
    const int wm = warp & 3, wn = warp >> 2;
#pragma unroll
    for (int mt = 0; mt < 2; mt++)
#pragma unroll
        for (int nt = 0; nt < 8; nt++) {
            const float* c = acc[mt * 8 + nt];
            const int m = m0 + wm * 32 + mt * 16 + (l >> 2);
            const int n = n0 + wn * 64 + nt * 8 + (l & 3) * 2;
            const float bb0 = bias[n], bb1 = bias[n + 1];
#pragma unroll
            for (int h2 = 0; h2 < 2; h2++) {
                const size_t mm = m + h2 * 8;
                float v0 = c[h2 * 2 + 0] + bb0;
                float v1 = c[h2 * 2 + 1] + bb1;
                if (z == 0) {
                    *(float2*)&g_Qp[mm * 512 + n] = make_float2(v0, v1);
                    *(unsigned*)&outB[mm * 512 + n] =
                        pack2bf(v0 * SCALE_, v1 * SCALE_);
                } else {
                    *(unsigned*)&outB[mm * 512 + n] = pack2bf(v0, v1);
                }
            }
        }
}

// Wo GEMM: A split bf16 (X1hi/lo), 3 passes, epilogue Xres + relu -> f32
__global__ __launch_bounds__(256, 2) void gemm_wo(
    const float* __restrict__ bias, const float* __restrict__ Xres,
    float* __restrict__ outF)
{
    __shared__ bf16 As[2 * BUFE], Bs[2 * BUFE];
    float acc[16][4];
#pragma unroll
    for (int i = 0; i < 16; i++)
#pragma unroll
        for (int j = 0; j < 4; j++) acc[i][j] = 0.f;

    const int m0 = blockIdx.y * 128, n0 = blockIdx.x * 128;
    for (int p = 0; p < 3; p++) {
        const bf16* Ag = ((p == 2) ? g_X1lo : g_X1hi) + (size_t)m0 * 512;
        const bf16* Bg = ((p == 1) ? g_Wot_lo : g_Wot_hi) + (size_t)n0 * 512;
        mainloop(Ag, Bg, As, Bs, acc);
    }

    const int tid = threadIdx.x, l = tid & 31, warp = tid >> 5;
    const int wm = warp & 3, wn = warp >> 2;
#pragma unroll
    for (int mt = 0; mt < 2; mt++)
#pragma unroll
        for (int nt = 0; nt < 8; nt++) {
            const float* c = acc[mt * 8 + nt];
            const int m = m0 + wm * 32 + mt * 16 + (l >> 2);
            const int n = n0 + wn * 64 + nt * 8 + (l & 3) * 2;
            const float bb0 = bias[n], bb1 = bias[n + 1];
#pragma unroll
            for (int h2 = 0; h2 < 2; h2++) {
                const size_t mm = m + h2 * 8;
                float v0 = c[h2 * 2 + 0] + bb0;
                float v1 = c[h2 * 2 + 1] + bb1;
                float2 xr = *(const float2*)&Xres[mm * 512 + n];
                *(float2*)&outF[mm * 512 + n] = make_float2(
                    xr.x + fmaxf(v0, 0.f), xr.y + fmaxf(v1, 0.f));
            }
        }
}

// ===== flash attention: 2 q-tiles per CTA, K/V reused; 1 CTA/SM, no spills =====
#define FS 72

__global__ __launch_bounds__(256, 1) void flash_attn(
    const bf16* __restrict__ Qb, const bf16* __restrict__ Kb,
    const bf16* __restrict__ Vb, const float* __restrict__ Qpf,
    float* __restrict__ Oh)
{
    __shared__ bf16 Ksm[128 * FS];
    __shared__ bf16 Vsm[128 * FS];

    const int tid = threadIdx.x, l = tid & 31, w = tid >> 5;
    const int qt2 = blockIdx.x, bh = blockIdx.y;
    const int b = bh >> 3, h = bh & 7;
    const unsigned sK = smem_u32(Ksm), sV = smem_u32(Vsm);

    const bf16* Qg = Qb + ((size_t)(b * 1024 + qt2 * 256)) * 512 + h * 64;
    const bf16* Kg = Kb + ((size_t)(b * 1024)) * 512 + h * 64;
    const bf16* Vg = Vb + ((size_t)(b * 1024)) * 512 + h * 64;

    // load both Q tiles' persistent A-fragments (staged through Ksm)
    unsigned qa[2][4][4];
#pragma unroll 1
    for (int qi = 0; qi < 2; qi++) {
#pragma unroll
        for (int i = 0; i < 4; i++) {
            int idx = tid + i * 256, r = idx >> 3, c8 = idx & 7;
            *(uint4*)(Ksm + r * FS + c8 * 8) =
                *(const uint4*)(Qg + (size_t)(qi * 128 + r) * 512 + c8 * 8);
        }
        __syncthreads();
        const int row = w * 16 + (l & 15);
        const int colb = (l >> 4) * 8;
#pragma unroll
        for (int j = 0; j < 4; j++) {
            unsigned ad = sK + (unsigned)((row * FS + j * 16 + colb) * 2);
            LDSM_X4(qa[qi][j][0], qa[qi][j][1], qa[qi][j][2], qa[qi][j][3], ad);
        }
        __syncthreads();
    }

    float oacc[2][8][4];
#pragma unroll
    for (int qi = 0; qi < 2; qi++)
#pragma unroll
        for (int i = 0; i < 8; i++)
#pragma unroll
            for (int j = 0; j < 4; j++) oacc[qi][i][j] = 0.f;
    float mrow[2][2], lrow[2][2];
#pragma unroll
    for (int qi = 0; qi < 2; qi++) {
        mrow[qi][0] = -1e30f; mrow[qi][1] = -1e30f;
        lrow[qi][0] = 0.f;    lrow[qi][1] = 0.f;
    }

    const int g = l >> 3, l8 = l & 7;

    for (int kt = 0; kt < 8; kt++) {
#pragma unroll
        for (int i = 0; i < 4; i++) {
            int idx = tid + i * 256, r = idx >> 3, c8 = idx & 7;
            size_t go = (size_t)(kt * 128 + r) * 512 + c8 * 8;
            *(uint4*)(Ksm + r * FS + c8 * 8) = *(const uint4*)(Kg + go);
            *(uint4*)(Vsm + r * FS + c8 * 8) = *(const uint4*)(Vg + go);
        }
        __syncthreads();

#pragma unroll 1
        for (int qi = 0; qi < 2; qi++) {
            // S = Q K^T (Q pre-scaled)
            float sc[16][4];
#pragma unroll
            for (int i = 0; i < 16; i++)
#pragma unroll
                for (int j = 0; j < 4; j++) sc[i][j] = 0.f;
#pragma unroll
            for (int s = 0; s < 4; s++) {
#pragma unroll
                for (int t = 0; t < 8; t++) {
                    unsigned r0, r1, r2, r3;
                    unsigned ad = sK + (unsigned)(((t * 16 + (g >> 1) * 8 + l8) * FS
                                                  + s * 16 + (g & 1) * 8) * 2);
                    LDSM_X4(r0, r1, r2, r3, ad);
                    unsigned bb0[2] = { r0, r1 }, bb1[2] = { r2, r3 };
                    MMA16816(sc[2 * t],     qa[qi][s], bb0);
                    MMA16816(sc[2 * t + 1], qa[qi][s], bb1);
                }
            }

            // online softmax
            float mx0 = -1e30f, mx1 = -1e30f;
#pragma unroll
            for (int t = 0; t < 16; t++) {
                mx0 = fmaxf(mx0, fmaxf(sc[t][0], sc[t][1]));
                mx1 = fmaxf(mx1, fmaxf(sc[t][2], sc[t][3]));
            }
            mx0 = fmaxf(mx0, __shfl_xor_sync(~0u, mx0, 1));
            mx0 = fmaxf(mx0, __shfl_xor_sync(~0u, mx0, 2));
            mx1 = fmaxf(mx1, __shfl_xor_sync(~0u, mx1, 1));
            mx1 = fmaxf(mx1, __shfl_xor_sync(~0u, mx1, 2));
            const float mn0 = fmaxf(mrow[qi][0], mx0);
            const float mn1 = fmaxf(mrow[qi][1], mx1);
            const float a0 = __expf(mrow[qi][0] - mn0);
            const float a1 = __expf(mrow[qi][1] - mn1);
            mrow[qi][0] = mn0; mrow[qi][1] = mn1;

            float sum0 = 0.f, sum1 = 0.f;
            unsigned pa[8][4];
#pragma unroll
            for (int t = 0; t < 8; t++) {
                float e00 = __expf(sc[2 * t][0] - mn0);
                float e01 = __expf(sc[2 * t][1] - mn0);
                float e10 = __expf(sc[2 * t][2] - mn1);
                float e11 = __expf(sc[2 * t][3] - mn1);
                float f00 = __expf(sc[2 * t + 1][0] - mn0);
                float f01 = __expf(sc[2 * t + 1][1] - mn0);
                float f10 = __expf(sc[2 * t + 1][2] - mn1);
                float f11 = __expf(sc[2 * t + 1][3] - mn1);
                sum0 += e00 + e01 + f00 + f01;
                sum1 += e10 + e11 + f10 + f11;
                pa[t][0] = pack2bf(e00, e01);
                pa[t][1] = pack2bf(e10, e11);
                pa[t][2] = pack2bf(f00, f01);
                pa[t][3] = pack2bf(f10, f11);
            }
            sum0 += __shfl_xor_sync(~0u, sum0, 1);
            sum0 += __shfl_xor_sync(~0u, sum0, 2);
            sum1 += __shfl_xor_sync(~0u, sum1, 1);
            sum1 += __shfl_xor_sync(~0u, sum1, 2);
            lrow[qi][0] = lrow[qi][0] * a0 + sum0;
            lrow[qi][1] = lrow[qi][1] * a1 + sum1;
#pragma unroll
            for (int d = 0; d < 8; d++) {
                oacc[qi][d][0] *= a0; oacc[qi][d][1] *= a0;
                oacc[qi][d][2] *= a1; oacc[qi][d][3] *= a1;
            }

            // O += P V
#pragma unroll
            for (int s2 = 0; s2 < 8; s2++) {
#pragma unroll
                for (int gd = 0; gd < 4; gd++) {
                    unsigned r0, r1, r2, r3;
                    unsigned ad = sV + (unsigned)(((s2 * 16 + (g & 1) * 8 + l8) * FS
                                                  + gd * 16 + (g >> 1) * 8) * 2);
                    LDSM_X4T(r0, r1, r2, r3, ad);
                    unsigned vb0[2] = { r0, r1 }, vb1[2] = { r2, r3 };
                    MMA16816(oacc[qi][2 * gd],     pa[s2], vb0);
                    MMA16816(oacc[qi][2 * gd + 1], pa[s2], vb1);
                }
            }
        }
        __syncthreads();
    }

#pragma unroll 1
    for (int qi = 0; qi < 2; qi++) {
        const float inv0 = 1.f / lrow[qi][0], inv1 = 1.f / lrow[qi][1];
        const int r0 = w * 16 + (l >> 2), r1 = r0 + 8;
        const int cb = 2 * (l & 3);
        const size_t base0 =
            ((size_t)(b * 1024 + qt2 * 256 + qi * 128 + r0)) * 512 + h * 64;
        const size_t base1 =
            ((size_t)(b * 1024 + qt2 * 256 + qi * 128 + r1)) * 512 + h * 64;
#pragma unroll
        for (int t = 0; t < 8; t++) {
            const int d = t * 8 + cb;
            float2 q0 = *(const float2*)&Qpf[base0 + d];
            float2 q1 = *(const float2*)&Qpf[base1 + d];
            *(float2*)&Oh[base0 + d] = make_float2(q0.x + oacc[qi][t][0] * inv0,
                                                   q0.y + oacc[qi][t][1] * inv0);
            *(float2*)&Oh[base1 + d] = make_float2(q1.x + oacc[qi][t][2] * inv1,
                                                   q1.y + oacc[qi][t][3] * inv1);
        }
    }
}

// Q and K fp32->bf16 conversion: y=0 Q (hi+lo), y=1 K (hi)
__global__ void conv_qk(const float* __restrict__ Q, const float* __restrict__ K,
                        int n4)
{
    int i = blockIdx.x * blockDim.x + threadIdx.x;
    if (i >= n4) return;
    if (blockIdx.y == 0) {
        float4 x = ((const float4*)Q)[i];
        uint2 hp; hp.x = pack2bf(x.x, x.y); hp.y = pack2bf(x.z, x.w);
        ((uint2*)g_Qhi)[i] = hp;
        float h0 = __bfloat162float(__float2bfloat16_rn(x.x));
        float h1 = __bfloat162float(__float2bfloat16_rn(x.y));
        float h2 = __bfloat162float(__float2bfloat16_rn(x.z));
        float h3 = __bfloat162float(__float2bfloat16_rn(x.w));
        uint2 lp; lp.x = pack2bf(x.x - h0, x.y - h1); lp.y = pack2bf(x.z - h2, x.w - h3);
        ((uint2*)g_Qlo)[i] = lp;
    } else {
        float4 x = ((const float4*)K)[i];
        uint2 hp; hp.x = pack2bf(x.x, x.y); hp.y = pack2bf(x.z, x.w);
        ((uint2*)g_Khi)[i] = hp;
    }
}

__global__ void convT_all(const float* __restrict__ Wq, const float* __restrict__ Wk,
                          const float* __restrict__ Wv, const float* __restrict__ Wo)
{
    __shared__ float t[32][33];
    const int tx = threadIdx.x & 31, ty = threadIdx.x >> 5;
    const int k0 = blockIdx.y * 32, n0 = blockIdx.x * 32;
    const int z = blockIdx.z;
    const float* W = (z == 0) ? Wq : (z == 1) ? Wk : (z == 2) ? Wv : Wo;
    bf16* Thi = (z == 0) ? g_Wqt_hi : (z == 1) ? g_Wkt : (z == 2) ? g_Wvt : g_Wot_hi;
    bf16* Tlo = (z == 0) ? g_Wqt_lo : (z == 3) ? g_Wot_lo : (bf16*)0;
#pragma unroll
    for (int i = 0; i < 4; i++)
        t[ty + 8 * i][tx] = W[(size_t)(k0 + ty + 8 * i) * 512 + n0 + tx];
    __syncthreads();
#pragma unroll
    for (int i = 0; i < 4; i++) {
        int n = n0 + ty + 8 * i;
        float x = t[tx][ty + 8 * i];
        bf16 h = __float2bfloat16_rn(x);
        Thi[(size_t)n * 512 + k0 + tx] = h;
        if (Tlo) Tlo[(size_t)n * 512 + k0 + tx] = __float2bfloat16_rn(x - __bfloat162float(h));
    }
}

__global__ __launch_bounds__(256) void ln512(
    const float* __restrict__ X, const float* __restrict__ g,
    const float* __restrict__ bb, float* __restrict__ Y,
    bf16* __restrict__ Hi, bf16* __restrict__ Lo)
{
    const size_t row = blockIdx.x;
    const int tid = threadIdx.x;
    const float* x = X + row * 512;
    const float v0 = x[tid], v1 = x[tid + 256];
    float s = v0 + v1, sq = v0 * v0 + v1 * v1;
    __shared__ float red[16];
#pragma unroll
    for (int off = 16; off; off >>= 1) {
        s  += __shfl_xor_sync(~0u, s,  off);
        sq += __shfl_xor_sync(~0u, sq, off);
    }
    const int wid = tid >> 5, lane = tid & 31;
    if (lane == 0) { red[wid * 2] = s; red[wid * 2 + 1] = sq; }
    __syncthreads();
    float sum = 0.f, sumsq = 0.f;
#pragma unroll
    for (int w = 0; w < 8; w++) { sum += red[w * 2]; sumsq += red[w * 2 + 1]; }
    const float mean = sum * (1.f / 512.f);
    const float var  = sumsq * (1.f / 512.f) - mean * mean;
    const float r    = rsqrtf(var + 1e-5f);
    const float y0 = (v0 - mean) * r * g[tid]       + bb[tid];
    const float y1 = (v1 - mean) * r * g[tid + 256] + bb[tid + 256];
    Y[row * 512 + tid]       = y0;
    Y[row * 512 + tid + 256] = y1;
    if (Hi) {
        bf16 h0 = __float2bfloat16_rn(y0), h1 = __float2bfloat16_rn(y1);
        Hi[row * 512 + tid]       = h0;
        Hi[row * 512 + tid + 256] = h1;
        Lo[row * 512 + tid]       = __float2bfloat16_rn(y0 - __bfloat162float(h0));
        Lo[row * 512 + tid + 256] = __float2bfloat16_rn(y1 - __bfloat162float(h1));
    }
}

extern "C" void kernel_launch(void* const* d_in, const int* in_sizes, int n_in,
                              void* d_out, int out_size)
{
    const float* Q  = (const float*)d_in[0];
    const float* K  = (const float*)d_in[1];
    const float* Wq = (const float*)d_in[2];
    const float* bq = (const float*)d_in[3];
    const float* Wk = (const float*)d_in[4];
    const float* bk = (const float*)d_in[5];
    const float* Wv = (const float*)d_in[6];
    const float* bv = (const float*)d_in[7];
    const float* Wo = (const float*)d_in[8];
    const float* bo = (const float*)d_in[9];
    const float* g0 = (const float*)d_in[10];
    const float* b0 = (const float*)d_in[11];
    const float* g1 = (const float*)d_in[12];
    const float* b1 = (const float*)d_in[13];
    float* out = (float*)d_out;

    bf16 *Qpb, *Kpb, *Vpb;
    float *Qp, *Oh, *X1, *Y;
    cudaGetSymbolAddress((void**)&Qp,  g_Qp);
    cudaGetSymbolAddress((void**)&Qpb, g_Qpb);
    cudaGetSymbolAddress((void**)&Kpb, g_Kpb);
    cudaGetSymbolAddress((void**)&Vpb, g_Vpb);
    cudaGetSymbolAddress((void**)&Oh,  g_Oh);
    cudaGetSymbolAddress((void**)&X1,  g_X1);
    cudaGetSymbolAddress((void**)&Y,   g_Y);

    bf16 *X1hi, *X1lo;
    cudaGetSymbolAddress((void**)&X1hi, g_X1hi);
    cudaGetSymbolAddress((void**)&X1lo, g_X1lo);

    const int n4 = MROWS * DV_ / 4;

    conv_qk<<<dim3((n4 + 255) / 256, 2), 256>>>(Q, K, n4);
    convT_all<<<dim3(16, 16, 4), 256>>>(Wq, Wk, Wv, Wo);
    gemm_qkv<<<dim3(4, 64, 3), 256>>>(bq, bk, bv);
    flash_attn<<<dim3(4, 64), 256>>>(Qpb, Kpb, Vpb, Qp, Oh);
    ln512<<<MROWS, 256>>>(Oh, g0, b0, X1, X1hi, X1lo);
    gemm_wo<<<dim3(4, 64), 256>>>(bo, X1, Y);
    ln512<<<MROWS, 256>>>(Y, g1, b1, out, (bf16*)0, (bf16*)0);
}

// round 17
// speedup vs baseline: 1.0656x; 1.0656x over previous
#include <cuda_runtime.h>
#include <cuda_bf16.h>
#include <math.h>

typedef __nv_bfloat16 bf16;

#define B_    8
#define NQ_   1024
#define DV_   512
#define MROWS (B_ * NQ_)
#define SSTRIDE 40
#define BUFE (128 * SSTRIDE)
#define BUFB (BUFE * 2)
#define SCALE_ 0.04419417382415922f

__device__ bf16  g_Qhi[MROWS * DV_];
__device__ bf16  g_Qlo[MROWS * DV_];
__device__ bf16  g_Khi[MROWS * DV_];
__device__ bf16  g_Wqt_hi[DV_ * DV_];
__device__ bf16  g_Wqt_lo[DV_ * DV_];
__device__ bf16  g_Wkt[DV_ * DV_];
__device__ bf16  g_Wvt[DV_ * DV_];
__device__ bf16  g_Wot_hi[DV_ * DV_];
__device__ bf16  g_Wot_lo[DV_ * DV_];
__device__ float g_Qp [MROWS * DV_];
__device__ bf16  g_Qpb[MROWS * DV_];
__device__ bf16  g_Kpb[MROWS * DV_];
__device__ bf16  g_Vpb[MROWS * DV_];
__device__ float g_Oh [MROWS * DV_];
__device__ float g_X1 [MROWS * DV_];
__device__ bf16  g_X1hi[MROWS * DV_];
__device__ bf16  g_X1lo[MROWS * DV_];
__device__ float g_Y  [MROWS * DV_];

__device__ __forceinline__ unsigned smem_u32(const void* p) {
    unsigned a;
    asm("{ .reg .u64 t; cvta.to.shared.u64 t, %1; cvt.u32.u64 %0, t; }" : "=r"(a) : "l"(p));
    return a;
}
__device__ __forceinline__ unsigned pack2bf(float a, float b) {
    __nv_bfloat162 t = __floats2bfloat162_rn(a, b);
    return *reinterpret_cast<unsigned*>(&t);
}

#define LDSM_X4(R0, R1, R2, R3, ADDR) \
    asm volatile("ldmatrix.sync.aligned.m8n8.x4.shared.b16 {%0,%1,%2,%3}, [%4];" \
                 : "=r"(R0), "=r"(R1), "=r"(R2), "=r"(R3) : "r"(ADDR))

#define LDSM_X4T(R0, R1, R2, R3, ADDR) \
    asm volatile("ldmatrix.sync.aligned.m8n8.x4.trans.shared.b16 {%0,%1,%2,%3}, [%4];" \
                 : "=r"(R0), "=r"(R1), "=r"(R2), "=r"(R3) : "r"(ADDR))

#define MMA16816(D, A, Bb) \
    asm volatile("mma.sync.aligned.m16n8k16.row.col.f32.bf16.bf16.f32 " \
                 "{%0,%1,%2,%3}, {%4,%5,%6,%7}, {%8,%9}, {%0,%1,%2,%3};" \
                 : "+f"((D)[0]), "+f"((D)[1]), "+f"((D)[2]), "+f"((D)[3]) \
                 : "r"((A)[0]), "r"((A)[1]), "r"((A)[2]), "r"((A)[3]), \
                   "r"((Bb)[0]), "r"((Bb)[1]))

#define CPA16(DST, SRC) \
    asm volatile("cp.async.cg.shared.global [%0], [%1], 16;" :: "r"(DST), "l"(SRC))
#define CPA_COMMIT() asm volatile("cp.async.commit_group;")
#define CPA_WAIT1()  asm volatile("cp.async.wait_group 1;")
#define CPA_WAIT0()  asm volatile("cp.async.wait_group 0;")

// Block tile 128x128, 8 warps (4m x 2n), K=512 in chunks of 32.
// cp.async double-buffered: prefetch, commit, WAIT1, sync, compute, sync.
__device__ __forceinline__ void mainloop(
    const bf16* __restrict__ A, const bf16* __restrict__ B,
    bf16* As, bf16* Bs, float (*acc)[4])
{
    const int tid  = threadIdx.x;
    const int l    = tid & 31;
    const int warp = tid >> 5;
    const int wm   = warp & 3, wn = warp >> 2;
    const unsigned sAu = smem_u32(As), sBu = smem_u32(Bs);

    const int ar0 = tid >> 2, ac0 = tid & 3;
    const int ar1 = ar0 + 64;
    const unsigned so0 = (unsigned)((ar0 * SSTRIDE + ac0 * 8) * 2);
    const unsigned so1 = (unsigned)((ar1 * SSTRIDE + ac0 * 8) * 2);

    unsigned aAddr[2];
#pragma unroll
    for (int mt = 0; mt < 2; mt++)
        aAddr[mt] = sAu + (unsigned)(((wm * 32 + mt * 16 + (l & 15)) * SSTRIDE
                                      + (l >> 4) * 8) * 2);
    const int g = l >> 3, l8 = l & 7;
    unsigned bAddr[4];
#pragma unroll
    for (int j = 0; j < 4; j++) {
        int row = wn * 64 + j * 16 + (g >> 1) * 8 + l8;
        bAddr[j] = sBu + (unsigned)((row * SSTRIDE + (g & 1) * 8) * 2);
    }

    CPA16(sAu + so0, A + (size_t)ar0 * 512 + ac0 * 8);
    CPA16(sAu + so1, A + (size_t)ar1 * 512 + ac0 * 8);
    CPA16(sBu + so0, B + (size_t)ar0 * 512 + ac0 * 8);
    CPA16(sBu + so1, B + (size_t)ar1 * 512 + ac0 * 8);
    CPA_COMMIT();

    for (int kc = 0; kc < 16; kc++) {
        if (kc + 1 < 16) {
            const int ko = (kc + 1) * 32;
            const unsigned bo = (unsigned)((kc + 1) & 1) * BUFB;
            CPA16(sAu + bo + so0, A + (size_t)ar0 * 512 + ko + ac0 * 8);
            CPA16(sAu + bo + so1, A + (size_t)ar1 * 512 + ko + ac0 * 8);
            CPA16(sBu + bo + so0, B + (size_t)ar0 * 512 + ko + ac0 * 8);
            CPA16(sBu + bo + so1, B + (size_t)ar1 * 512 + ko + ac0 * 8);
            CPA_COMMIT();
            CPA_WAIT1();
        } else {
            CPA_WAIT0();
        }
        __syncthreads();
        const unsigned bo = (unsigned)(kc & 1) * BUFB;
#pragma unroll
        for (int s = 0; s < 2; s++) {
            unsigned af[2][4];
            LDSM_X4(af[0][0], af[0][1], af[0][2], af[0][3], aAddr[0] + bo + s * 32);
            LDSM_X4(af[1][0], af[1][1], af[1][2], af[1][3], aAddr[1] + bo + s * 32);
            unsigned bfm[8][2];
#pragma unroll
            for (int j = 0; j < 4; j++)
                LDSM_X4(bfm[2 * j][0], bfm[2 * j][1],
                        bfm[2 * j + 1][0], bfm[2 * j + 1][1], bAddr[j] + bo + s * 32);
#pragma unroll
            for (int mt = 0; mt < 2; mt++)
#pragma unroll
                for (int nt = 0; nt < 8; nt++)
                    MMA16816(acc[mt * 8 + nt], af[mt], bfm[nt]);
        }
        __syncthreads();
    }
}

// Merged Q/K/V projections: z=0 -> Qp (3-pass split, f32 + scaled bf16),
// z=1 -> Kp (1-pass, bf16), z=2 -> Vp (1-pass, bf16)
__global__ __launch_bounds__(256, 2) void gemm_qkv(
    const float* __restrict__ bq, const float* __restrict__ bk,
    const float* __restrict__ bv)
{
    __shared__ bf16 As[2 * BUFE], Bs[2 * BUFE];
    float acc[16][4];
#pragma unroll
    for (int i = 0; i < 16; i++)
#pragma unroll
        for (int j = 0; j < 4; j++) acc[i][j] = 0.f;

    const int m0 = blockIdx.y * 128, n0 = blockIdx.x * 128;
    const int z = blockIdx.z;

    if (z == 0) {
        for (int p = 0; p < 3; p++) {
            const bf16* Ag = ((p == 2) ? g_Qlo : g_Qhi) + (size_t)m0 * 512;
            const bf16* Bg = ((p == 1) ? g_Wqt_lo : g_Wqt_hi) + (size_t)n0 * 512;
            mainloop(Ag, Bg, As, Bs, acc);
        }
    } else {
        const bf16* Bw = (z == 1) ? g_Wkt : g_Wvt;
        mainloop(g_Khi + (size_t)m0 * 512, Bw + (size_t)n0 * 512, As, Bs, acc);
    }

    const float* bias = (z == 0) ? bq : (z == 1) ? bk : bv;
    bf16* outB = (z == 0) ? g_Qpb : (z == 1) ? g_Kpb : g_Vpb;

    const int tid = threadIdx.x, l = tid & 31, warp = tid >> 5;
    const int wm = warp & 3, wn = warp >> 2;
#pragma unroll
    for (int mt = 0; mt < 2; mt++)
#pragma unroll
        for (int nt = 0; nt < 8; nt++) {
            const float* c = acc[mt * 8 + nt];
            const int m = m0 + wm * 32 + mt * 16 + (l >> 2);
            const int n = n0 + wn * 64 + nt * 8 + (l & 3) * 2;
            const float bb0 = bias[n], bb1 = bias[n + 1];
#pragma unroll
            for (int h2 = 0; h2 < 2; h2++) {
                const size_t mm = m + h2 * 8;
                float v0 = c[h2 * 2 + 0] + bb0;
                float v1 = c[h2 * 2 + 1] + bb1;
                if (z == 0) {
                    *(float2*)&g_Qp[mm * 512 + n] = make_float2(v0, v1);
                    *(unsigned*)&outB[mm * 512 + n] =
                        pack2bf(v0 * SCALE_, v1 * SCALE_);
                } else {
                    *(unsigned*)&outB[mm * 512 + n] = pack2bf(v0, v1);
                }
            }
        }
}

// Wo GEMM: A split bf16 (X1hi/lo), 3 passes, epilogue Xres + relu -> f32
__global__ __launch_bounds__(256, 2) void gemm_wo(
    const float* __restrict__ bias, const float* __restrict__ Xres,
    float* __restrict__ outF)
{
    __shared__ bf16 As[2 * BUFE], Bs[2 * BUFE];
    float acc[16][4];
#pragma unroll
    for (int i = 0; i < 16; i++)
#pragma unroll
        for (int j = 0; j < 4; j++) acc[i][j] = 0.f;

    const int m0 = blockIdx.y * 128, n0 = blockIdx.x * 128;
    for (int p = 0; p < 3; p++) {
        const bf16* Ag = ((p == 2) ? g_X1lo : g_X1hi) + (size_t)m0 * 512;
        const bf16* Bg = ((p == 1) ? g_Wot_lo : g_Wot_hi) + (size_t)n0 * 512;
        mainloop(Ag, Bg, As, Bs, acc);
    }

    const int tid = threadIdx.x, l = tid & 31, warp = tid >> 5;
    const int wm = warp & 3, wn = warp >> 2;
#pragma unroll
    for (int mt = 0; mt < 2; mt++)
#pragma unroll
        for (int nt = 0; nt < 8; nt++) {
            const float* c = acc[mt * 8 + nt];
            const int m = m0 + wm * 32 + mt * 16 + (l >> 2);
            const int n = n0 + wn * 64 + nt * 8 + (l & 3) * 2;
            const float bb0 = bias[n], bb1 = bias[n + 1];
#pragma unroll
            for (int h2 = 0; h2 < 2; h2++) {
                const size_t mm = m + h2 * 8;
                float v0 = c[h2 * 2 + 0] + bb0;
                float v1 = c[h2 * 2 + 1] + bb1;
                float2 xr = *(const float2*)&Xres[mm * 512 + n];
                *(float2*)&outF[mm * 512 + n] = make_float2(
                    xr.x + fmaxf(v0, 0.f), xr.y + fmaxf(v1, 0.f));
            }
        }
}

// ===== flash attention: 2 q-tiles per CTA, K/V reused; pa packed into sc =====
#define FS 72

__global__ __launch_bounds__(256, 2) void flash_attn(
    const bf16* __restrict__ Qb, const bf16* __restrict__ Kb,
    const bf16* __restrict__ Vb, const float* __restrict__ Qpf,
    float* __restrict__ Oh)
{
    __shared__ bf16 Ksm[128 * FS];
    __shared__ bf16 Vsm[128 * FS];

    const int tid = threadIdx.x, l = tid & 31, w = tid >> 5;
    const int qt2 = blockIdx.x, bh = blockIdx.y;
    const int b = bh >> 3, h = bh & 7;
    const unsigned sK = smem_u32(Ksm), sV = smem_u32(Vsm);

    const bf16* Qg = Qb + ((size_t)(b * 1024 + qt2 * 256)) * 512 + h * 64;
    const bf16* Kg = Kb + ((size_t)(b * 1024)) * 512 + h * 64;
    const bf16* Vg = Vb + ((size_t)(b * 1024)) * 512 + h * 64;

    // load both Q tiles' persistent A-fragments (staged through Ksm)
    unsigned qa[2][4][4];
#pragma unroll 1
    for (int qi = 0; qi < 2; qi++) {
#pragma unroll
        for (int i = 0; i < 4; i++) {
            int idx = tid + i * 256, r = idx >> 3, c8 = idx & 7;
            *(uint4*)(Ksm + r * FS + c8 * 8) =
                *(const uint4*)(Qg + (size_t)(qi * 128 + r) * 512 + c8 * 8);
        }
        __syncthreads();
        const int row = w * 16 + (l & 15);
        const int colb = (l >> 4) * 8;
#pragma unroll
        for (int j = 0; j < 4; j++) {
            unsigned ad = sK + (unsigned)((row * FS + j * 16 + colb) * 2);
            LDSM_X4(qa[qi][j][0], qa[qi][j][1], qa[qi][j][2], qa[qi][j][3], ad);
        }
        __syncthreads();
    }

    float oacc[2][8][4];
#pragma unroll
    for (int qi = 0; qi < 2; qi++)
#pragma unroll
        for (int i = 0; i < 8; i++)
#pragma unroll
            for (int j = 0; j < 4; j++) oacc[qi][i][j] = 0.f;
    float mrow[2][2], lrow[2][2];
#pragma unroll
    for (int qi = 0; qi < 2; qi++) {
        mrow[qi][0] = -1e30f; mrow[qi][1] = -1e30f;
        lrow[qi][0] = 0.f;    lrow[qi][1] = 0.f;
    }

    const int g = l >> 3, l8 = l & 7;

    for (int kt = 0; kt < 8; kt++) {
#pragma unroll
        for (int i = 0; i < 4; i++) {
            int idx = tid + i * 256, r = idx >> 3, c8 = idx & 7;
            size_t go = (size_t)(kt * 128 + r) * 512 + c8 * 8;
            *(uint4*)(Ksm + r * FS + c8 * 8) = *(const uint4*)(Kg + go);
            *(uint4*)(Vsm + r * FS + c8 * 8) = *(const uint4*)(Vg + go);
        }
        __syncthreads();

#pragma unroll 1
        for (int qi = 0; qi < 2; qi++) {
            // S = Q K^T (Q pre-scaled)
            float sc[16][4];
#pragma unroll
            for (int i = 0; i < 16; i++)
#pragma unroll
                for (int j = 0; j < 4; j++) sc[i][j] = 0.f;
#pragma unroll
            for (int s = 0; s < 4; s++) {
#pragma unroll
                for (int t = 0; t < 8; t++) {
                    unsigned r0, r1, r2, r3;
                    unsigned ad = sK + (unsigned)(((t * 16 + (g >> 1) * 8 + l8) * FS
                                                  + s * 16 + (g & 1) * 8) * 2);
                    LDSM_X4(r0, r1, r2, r3, ad);
                    unsigned bb0[2] = { r0, r1 }, bb1[2] = { r2, r3 };
                    MMA16816(sc[2 * t],     qa[qi][s], bb0);
                    MMA16816(sc[2 * t + 1], qa[qi][s], bb1);
                }
            }

            // online softmax
            float mx0 = -1e30f, mx1 = -1e30f;
#pragma unroll
            for (int t = 0; t < 16; t++) {
                mx0 = fmaxf(mx0, fmaxf(sc[t][0], sc[t][1]));
                mx1 = fmaxf(mx1, fmaxf(sc[t][2], sc[t][3]));
            }
            mx0 = fmaxf(mx0, __shfl_xor_sync(~0u, mx0, 1));
            mx0 = fmaxf(mx0, __shfl_xor_sync(~0u, mx0, 2));
            mx1 = fmaxf(mx1, __shfl_xor_sync(~0u, mx1, 1));
            mx1 = fmaxf(mx1, __shfl_xor_sync(~0u, mx1, 2));
            const float mn0 = fmaxf(mrow[qi][0], mx0);
            const float mn1 = fmaxf(mrow[qi][1], mx1);
            const float a0 = __expf(mrow[qi][0] - mn0);
            const float a1 = __expf(mrow[qi][1] - mn1);
            mrow[qi][0] = mn0; mrow[qi][1] = mn1;

            // exp + pack IN PLACE into sc storage (frees pa register pressure):
            // packed pa[t][k] lives at sc[2t][k] reinterpreted as unsigned.
            float sum0 = 0.f, sum1 = 0.f;
#pragma unroll
            for (int t = 0; t < 8; t++) {
                float e00 = __expf(sc[2 * t][0] - mn0);
                float e01 = __expf(sc[2 * t][1] - mn0);
                float e10 = __expf(sc[2 * t][2] - mn1);
                float e11 = __expf(sc[2 * t][3] - mn1);
                float f00 = __expf(sc[2 * t + 1][0] - mn0);
                float f01 = __expf(sc[2 * t + 1][1] - mn0);
                float f10 = __expf(sc[2 * t + 1][2] - mn1);
                float f11 = __expf(sc[2 * t + 1][3] - mn1);
                sum0 += e00 + e01 + f00 + f01;
                sum1 += e10 + e11 + f10 + f11;
                sc[2 * t][0] = __uint_as_float(pack2bf(e00, e01));
                sc[2 * t][1] = __uint_as_float(pack2bf(e10, e11));
                sc[2 * t][2] = __uint_as_float(pack2bf(f00, f01));
                sc[2 * t][3] = __uint_as_float(pack2bf(f10, f11));
            }
            sum0 += __shfl_xor_sync(~0u, sum0, 1);
            sum0 += __shfl_xor_sync(~0u, sum0, 2);
            sum1 += __shfl_xor_sync(~0u, sum1, 1);
            sum1 += __shfl_xor_sync(~0u, sum1, 2);
            lrow[qi][0] = lrow[qi][0] * a0 + sum0;
            lrow[qi][1] = lrow[qi][1] * a1 + sum1;
#pragma unroll
            for (int d = 0; d < 8; d++) {
                oacc[qi][d][0] *= a0; oacc[qi][d][1] *= a0;
                oacc[qi][d][2] *= a1; oacc[qi][d][3] *= a1;
            }

            // O += P V (P fragments read from packed sc storage)
#pragma unroll
            for (int s2 = 0; s2 < 8; s2++) {
                unsigned pa0 = __float_as_uint(sc[2 * s2][0]);
                unsigned pa1 = __float_as_uint(sc[2 * s2][1]);
                unsigned pa2 = __float_as_uint(sc[2 * s2][2]);
                unsigned pa3 = __float_as_uint(sc[2 * s2][3]);
                unsigned paf[4] = { pa0, pa1, pa2, pa3 };
#pragma unroll
                for (int gd = 0; gd < 4; gd++) {
                    unsigned r0, r1, r2, r3;
                    unsigned ad = sV + (unsigned)(((s2 * 16 + (g & 1) * 8 + l8) * FS
                                                  + gd * 16 + (g >> 1) * 8) * 2);
                    LDSM_X4T(r0, r1, r2, r3, ad);
                    unsigned vb0[2] = { r0, r1 }, vb1[2] = { r2, r3 };
                    MMA16816(oacc[qi][2 * gd],     paf, vb0);
                    MMA16816(oacc[qi][2 * gd + 1], paf, vb1);
                }
            }
        }
        __syncthreads();
    }

#pragma unroll 1
    for (int qi = 0; qi < 2; qi++) {
        const float inv0 = 1.f / lrow[qi][0], inv1 = 1.f / lrow[qi][1];
        const int r0 = w * 16 + (l >> 2), r1 = r0 + 8;
        const int cb = 2 * (l & 3);
        const size_t base0 =
            ((size_t)(b * 1024 + qt2 * 256 + qi * 128 + r0)) * 512 + h * 64;
        const size_t base1 =
            ((size_t)(b * 1024 + qt2 * 256 + qi * 128 + r1)) * 512 + h * 64;
#pragma unroll
        for (int t = 0; t < 8; t++) {
            const int d = t * 8 + cb;
            float2 q0 = *(const float2*)&Qpf[base0 + d];
            float2 q1 = *(const float2*)&Qpf[base1 + d];
            *(float2*)&Oh[base0 + d] = make_float2(q0.x + oacc[qi][t][0] * inv0,
                                                   q0.y + oacc[qi][t][1] * inv0);
            *(float2*)&Oh[base1 + d] = make_float2(q1.x + oacc[qi][t][2] * inv1,
                                                   q1.y + oacc[qi][t][3] * inv1);
        }
    }
}

// Q and K fp32->bf16 conversion: y=0 Q (hi+lo), y=1 K (hi)
__global__ void conv_qk(const float* __restrict__ Q, const float* __restrict__ K,
                        int n4)
{
    int i = blockIdx.x * blockDim.x + threadIdx.x;
    if (i >= n4) return;
    if (blockIdx.y == 0) {
        float4 x = ((const float4*)Q)[i];
        uint2 hp; hp.x = pack2bf(x.x, x.y); hp.y = pack2bf(x.z, x.w);
        ((uint2*)g_Qhi)[i] = hp;
        float h0 = __bfloat162float(__float2bfloat16_rn(x.x));
        float h1 = __bfloat162float(__float2bfloat16_rn(x.y));
        float h2 = __bfloat162float(__float2bfloat16_rn(x.z));
        float h3 = __bfloat162float(__float2bfloat16_rn(x.w));
        uint2 lp; lp.x = pack2bf(x.x - h0, x.y - h1); lp.y = pack2bf(x.z - h2, x.w - h3);
        ((uint2*)g_Qlo)[i] = lp;
    } else {
        float4 x = ((const float4*)K)[i];
        uint2 hp; hp.x = pack2bf(x.x, x.y); hp.y = pack2bf(x.z, x.w);
        ((uint2*)g_Khi)[i] = hp;
    }
}

__global__ void convT_all(const float* __restrict__ Wq, const float* __restrict__ Wk,
                          const float* __restrict__ Wv, const float* __restrict__ Wo)
{
    __shared__ float t[32][33];
    const int tx = threadIdx.x & 31, ty = threadIdx.x >> 5;
    const int k0 = blockIdx.y * 32, n0 = blockIdx.x * 32;
    const int z = blockIdx.z;
    const float* W = (z == 0) ? Wq : (z == 1) ? Wk : (z == 2) ? Wv : Wo;
    bf16* Thi = (z == 0) ? g_Wqt_hi : (z == 1) ? g_Wkt : (z == 2) ? g_Wvt : g_Wot_hi;
    bf16* Tlo = (z == 0) ? g_Wqt_lo : (z == 3) ? g_Wot_lo : (bf16*)0;
#pragma unroll
    for (int i = 0; i < 4; i++)
        t[ty + 8 * i][tx] = W[(size_t)(k0 + ty + 8 * i) * 512 + n0 + tx];
    __syncthreads();
#pragma unroll
    for (int i = 0; i < 4; i++) {
        int n = n0 + ty + 8 * i;
        float x = t[tx][ty + 8 * i];
        bf16 h = __float2bfloat16_rn(x);
        Thi[(size_t)n * 512 + k0 + tx] = h;
        if (Tlo) Tlo[(size_t)n * 512 + k0 + tx] = __float2bfloat16_rn(x - __bfloat162float(h));
    }
}

__global__ __launch_bounds__(256) void ln512(
    const float* __restrict__ X, const float* __restrict__ g,
    const float* __restrict__ bb, float* __restrict__ Y,
    bf16* __restrict__ Hi, bf16* __restrict__ Lo)
{
    const size_t row = blockIdx.x;
    const int tid = threadIdx.x;
    const float* x = X + row * 512;
    const float v0 = x[tid], v1 = x[tid + 256];
    float s = v0 + v1, sq = v0 * v0 + v1 * v1;
    __shared__ float red[16];
#pragma unroll
    for (int off = 16; off; off >>= 1) {
        s  += __shfl_xor_sync(~0u, s,  off);
        sq += __shfl_xor_sync(~0u, sq, off);
    }
    const int wid = tid >> 5, lane = tid & 31;
    if (lane == 0) { red[wid * 2] = s; red[wid * 2 + 1] = sq; }
    __syncthreads();
    float sum = 0.f, sumsq = 0.f;
#pragma unroll
    for (int w = 0; w < 8; w++) { sum += red[w * 2]; sumsq += red[w * 2 + 1]; }
    const float mean = sum * (1.f / 512.f);
    const float var  = sumsq * (1.f / 512.f) - mean * mean;
    const float r    = rsqrtf(var + 1e-5f);
    const float y0 = (v0 - mean) * r * g[tid]       + bb[tid];
    const float y1 = (v1 - mean) * r * g[tid + 256] + bb[tid + 256];
    Y[row * 512 + tid]       = y0;
    Y[row * 512 + tid + 256] = y1;
    if (Hi) {
        bf16 h0 = __float2bfloat16_rn(y0), h1 = __float2bfloat16_rn(y1);
        Hi[row * 512 + tid]       = h0;
        Hi[row * 512 + tid + 256] = h1;
        Lo[row * 512 + tid]       = __float2bfloat16_rn(y0 - __bfloat162float(h0));
        Lo[row * 512 + tid + 256] = __float2bfloat16_rn(y1 - __bfloat162float(h1));
    }
}

extern "C" void kernel_launch(void* const* d_in, const int* in_sizes, int n_in,
                              void* d_out, int out_size)
{
    const float* Q  = (const float*)d_in[0];
    const float* K  = (const float*)d_in[1];
    const float* Wq = (const float*)d_in[2];
    const float* bq = (const float*)d_in[3];
    const float* Wk = (const float*)d_in[4];
    const float* bk = (const float*)d_in[5];
    const float* Wv = (const float*)d_in[6];
    const float* bv = (const float*)d_in[7];
    const float* Wo = (const float*)d_in[8];
    const float* bo = (const float*)d_in[9];
    const float* g0 = (const float*)d_in[10];
    const float* b0 = (const float*)d_in[11];
    const float* g1 = (const float*)d_in[12];
    const float* b1 = (const float*)d_in[13];
    float* out = (float*)d_out;

    bf16 *Qpb, *Kpb, *Vpb, *X1hi, *X1lo;
    float *Qp, *Oh, *X1, *Y;
    cudaGetSymbolAddress((void**)&Qp,  g_Qp);
    cudaGetSymbolAddress((void**)&Qpb, g_Qpb);
    cudaGetSymbolAddress((void**)&Kpb, g_Kpb);
    cudaGetSymbolAddress((void**)&Vpb, g_Vpb);
    cudaGetSymbolAddress((void**)&Oh,  g_Oh);
    cudaGetSymbolAddress((void**)&X1,  g_X1);
    cudaGetSymbolAddress((void**)&X1hi, g_X1hi);
    cudaGetSymbolAddress((void**)&X1lo, g_X1lo);
    cudaGetSymbolAddress((void**)&Y,   g_Y);

    const int n4 = MROWS * DV_ / 4;

    conv_qk<<<dim3((n4 + 255) / 256, 2), 256>>>(Q, K, n4);
    convT_all<<<dim3(16, 16, 4), 256>>>(Wq, Wk, Wv, Wo);
    gemm_qkv<<<dim3(4, 64, 3), 256>>>(bq, bk, bv);
    flash_attn<<<dim3(4, 64), 256>>>(Qpb, Kpb, Vpb, Qp, Oh);
    ln512<<<MROWS, 256>>>(Oh, g0, b0, X1, X1hi, X1lo);
    gemm_wo<<<dim3(4, 64), 256>>>(bo, X1, Y);
    ln512<<<MROWS, 256>>>(Y, g1, b1, out, (bf16*)0, (bf16*)0);
}